// round 3
// baseline (speedup 1.0000x reference)
#include <cuda_runtime.h>
#include <math.h>

// RRoIAlign:
//   K1: NCHW (8,32,160,160) -> NHWC scratch (8,160,160,32), vectorized both phases.
//   K2: one block per ROI: geometry for all 512 bins by all 512 threads (no
//       divergence), then 8 row-iterations of coalesced float4 gathers + blend +
//       smem transpose (double-buffered, 1 sync/row) + coalesced stores.

namespace {

constexpr int PH = 8;
constexpr int PW = 64;
constexpr int CC = 32;
constexpr int HH = 160;
constexpr int WW = 160;
constexpr int BB = 8;
constexpr float SCALE = 0.25f;

constexpr int IMG   = HH * WW * CC;          // floats per image (819200)
constexpr int ROWF  = WW * CC;               // floats per pixel-row (5120)
constexpr int GUARD = 524288;                // 2MB guard each side (zero-init, never written)

__device__ float g_nhwc[GUARD + (size_t)BB * IMG + GUARD];

// ---------------- K1: NCHW -> NHWC transpose (vectorized) ----------------
// tile layout: [c][x], row padded to 164 floats (164 mod 32 == 4).
__global__ __launch_bounds__(256) void transpose_kernel(const float* __restrict__ feat)
{
    __shared__ float tile[CC * 164];
    const int b = blockIdx.x / HH;
    const int y = blockIdx.x - b * HH;

    // phase 1: LDG.128 along x (coalesced), STS.128 into tile (conflict-free)
    const float* src = feat + (size_t)b * IMG + (size_t)y * WW;   // + c*25600 + x
#pragma unroll
    for (int f = threadIdx.x; f < CC * (WW / 4); f += 256) {      // 5 iters
        const int c  = f / (WW / 4);
        const int x4 = f - c * (WW / 4);
        const float4 v = __ldg(reinterpret_cast<const float4*>(src + (size_t)c * (HH * WW) + x4 * 4));
        *reinterpret_cast<float4*>(&tile[c * 164 + x4 * 4]) = v;
    }
    __syncthreads();

    // phase 2: 4x LDS.32 (<=2-way conflict), STG.128 coalesced to NHWC
    float* dst = g_nhwc + GUARD + (size_t)b * IMG + (size_t)y * ROWF;
#pragma unroll
    for (int g = threadIdx.x; g < (WW * CC) / 4; g += 256) {      // 5 iters
        const int x  = g >> 3;
        const int cg = g & 7;
        float4 v;
        v.x = tile[(4 * cg + 0) * 164 + x];
        v.y = tile[(4 * cg + 1) * 164 + x];
        v.z = tile[(4 * cg + 2) * 164 + x];
        v.w = tile[(4 * cg + 3) * 164 + x];
        *reinterpret_cast<float4*>(dst + (size_t)x * CC + 4 * cg) = v;
    }
}

// ---------------- K2: one block per ROI ----------------
__global__ __launch_bounds__(512) void rroi_gather_kernel(
    const float* __restrict__ rois,
    float* __restrict__ out)
{
    __shared__ int   s_base[PH * PW];                 // 512
    __shared__ float s_w0[PH * PW], s_w1[PH * PW], s_w2[PH * PW], s_w3[PH * PW];
    __shared__ float s_r[2][CC * 65];                 // double-buffered output tile

    const int n   = blockIdx.x;
    const int tid = threadIdx.x;

    // --- geometry: every thread computes its own bin (tid = ph*64 + pw) ---
    {
        const float2* rp = reinterpret_cast<const float2*>(rois + (size_t)n * 6);
        const float2 ra = __ldg(rp + 0);   // batch_idx, cx
        const float2 rb = __ldg(rp + 1);   // cy, h
        const float2 rc = __ldg(rp + 2);   // w, ang

        const int   bidx = (int)ra.x;
        const float cx = ra.y, cy = rb.x, hh = rb.y, ww = rc.x, ang = rc.y;

        const float theta = ang * 0.017453292519943295f;
        float sa, ca;
        sincosf(theta, &sa, &ca);

        const float Sx = ww * SCALE / (float)PW;
        const float Sy = hh * SCALE / (float)PH;
        const float dxc = -(float)PW * 0.5f;
        const float dyc = -(float)PH * 0.5f;
        const float Dx = cx * SCALE;
        const float Dy = cy * SCALE;

        const float M00 = ca * Sx;
        const float M01 = sa * Sy;
        const float M02 = M00 * dxc + M01 * dyc + Dx;
        const float M10 = -sa * Sx;
        const float M11 = ca * Sy;
        const float M12 = M10 * dxc + M11 * dyc + Dy;

        const float pw  = (float)(tid & (PW - 1));
        const float ph  = (float)(tid >> 6);
        const float pw1 = pw + 1.0f;
        const float ph1 = ph + 1.0f;

        const float X0 = M00 * pw  + M01 * ph  + M02;
        const float X1 = M00 * pw  + M01 * ph1 + M02;
        const float X2 = M00 * pw1 + M01 * ph  + M02;
        const float X3 = M00 * pw1 + M01 * ph1 + M02;
        const float Y0 = M10 * pw  + M11 * ph  + M12;
        const float Y1 = M10 * pw  + M11 * ph1 + M12;
        const float Y2 = M10 * pw1 + M11 * ph  + M12;
        const float Y3 = M10 * pw1 + M11 * ph1 + M12;

        const float xmn = fminf(fminf(X0, X1), fminf(X2, X3));
        const float xmx = fmaxf(fmaxf(X0, X1), fmaxf(X2, X3));
        const float ymn = fminf(fminf(Y0, Y1), fminf(Y2, Y3));
        const float ymx = fmaxf(fmaxf(Y0, Y1), fmaxf(Y2, Y3));

        const float left   = fmaxf(floorf(xmn + 0.5f), 0.0f);
        const float right  = fminf(floorf(xmx + 0.5f), (float)(WW - 1));
        const float top    = fmaxf(floorf(ymn + 0.5f), 0.0f);
        const float bottom = fminf(floorf(ymx + 0.5f), (float)(HH - 1));

        const float bcx = (left + right) * 0.5f;
        const float bcy = (top + bottom) * 0.5f;

        const float bl = floorf(bcx);
        const float br = ceilf(bcx);
        const float bt = floorf(bcy);
        const float bb = ceilf(bcy);
        const float rx = bcx - bl;
        const float ry = bcy - bt;

        const bool vl = (bl > -1.0f) && (bl < (float)WW);
        const bool vr = (br > -1.0f) && (br < (float)WW);
        const bool vt = (bt > -1.0f) && (bt < (float)HH);
        const bool vb = (bb > -1.0f) && (bb < (float)HH);

        // nonzero weight implies ceil==floor+1 on that axis, so the fixed 2x2
        // patch at (yt..yt+1, xl..xl+1) is exact; zero-weight taps may read the
        // zeroed guard band harmlessly.
        float wlt = (1.0f - rx) * (1.0f - ry);
        float wrt = rx * (1.0f - ry);
        float wlb = (1.0f - rx) * ry;
        float wrb = rx * ry;
        if (!(vt && vl)) wlt = 0.0f;
        if (!(vt && vr)) wrt = 0.0f;
        if (!(vb && vl)) wlb = 0.0f;
        if (!(vb && vr)) wrb = 0.0f;

        const int xl = (int)bl;
        const int yt = (int)bt;

        s_base[tid] = bidx * IMG + (yt * WW + xl) * CC;
        s_w0[tid] = wlt; s_w1[tid] = wrt; s_w2[tid] = wlb; s_w3[tid] = wrb;
    }
    __syncthreads();

    const int bin = tid >> 3;          // 0..63
    const int cg  = tid & 7;           // channel group (4 channels)
    const float* g = g_nhwc + GUARD;
    float* ob = out + (size_t)n * (CC * PH * PW);

#pragma unroll
    for (int r = 0; r < PH; r++) {
        const int p   = r & 1;
        const int idx = r * PW + bin;

        const int base  = s_base[idx] + cg * 4;
        const float wlt = s_w0[idx], wrt = s_w1[idx], wlb = s_w2[idx], wrb = s_w3[idx];

        const float4 t00 = *reinterpret_cast<const float4*>(g + base);
        const float4 t01 = *reinterpret_cast<const float4*>(g + base + CC);
        const float4 t10 = *reinterpret_cast<const float4*>(g + base + ROWF);
        const float4 t11 = *reinterpret_cast<const float4*>(g + base + ROWF + CC);

        float4 v;
        v.x = wlt * t00.x + wrt * t01.x + wlb * t10.x + wrb * t11.x;
        v.y = wlt * t00.y + wrt * t01.y + wlb * t10.y + wrb * t11.y;
        v.z = wlt * t00.z + wrt * t01.z + wlb * t10.z + wrb * t11.z;
        v.w = wlt * t00.w + wrt * t01.w + wlb * t10.w + wrb * t11.w;

        const int c0 = cg * 4;
        s_r[p][(c0 + 0) * 65 + bin] = v.x;        // conflict-free (pad 65)
        s_r[p][(c0 + 1) * 65 + bin] = v.y;
        s_r[p][(c0 + 2) * 65 + bin] = v.z;
        s_r[p][(c0 + 3) * 65 + bin] = v.w;

        __syncthreads();   // single sync per row; buffer p is safe to overwrite
                           // again only after the NEXT row's sync (double buffer)

#pragma unroll
        for (int i = tid; i < CC * PW; i += 512) {
            const int c = i >> 6;
            const int x = i & 63;
            ob[(size_t)c * (PH * PW) + r * PW + x] = s_r[p][c * 65 + x];   // coalesced
        }
    }
}

}  // namespace

extern "C" void kernel_launch(void* const* d_in, const int* in_sizes, int n_in,
                              void* d_out, int out_size) {
    const float* features = (const float*)d_in[0];
    const float* rois     = (const float*)d_in[1];
    float* out            = (float*)d_out;

    const int N = in_sizes[1] / 6;  // 1024

    transpose_kernel<<<BB * HH, 256>>>(features);
    rroi_gather_kernel<<<N, 512>>>(rois, out);
}

// round 5
// speedup vs baseline: 1.1892x; 1.1892x over previous
#include <cuda_runtime.h>
#include <math.h>

// RRoIAlign:
//   K1: NCHW (8,32,160,160) -> NHWC scratch (8,160,160,32), guard-banded.
//   K2: grid (1024 rois, 4 row-pairs) x 512 threads. 128 threads compute the
//       geometry of 128 bins (2 ph-rows) into smem; all 512 threads then gather
//       2 rows x 4 float4 taps (coalesced LDG.128, MLP=8), blend, stage via
//       padded smem (odd stride, conflict-free STS), and store coalesced
//       (4x LDS.32 + STG.128 — scalar reads because odd stride forbids LDS.128).

namespace {

constexpr int PH = 8;
constexpr int PW = 64;
constexpr int CC = 32;
constexpr int HH = 160;
constexpr int WW = 160;
constexpr int BB = 8;
constexpr float SCALE = 0.25f;

constexpr int IMG   = HH * WW * CC;          // 819200 floats per image
constexpr int ROWF  = WW * CC;               // 5120 floats per pixel-row
constexpr int GUARD = 524288;                // 2MB zero guard each side

__device__ float g_nhwc[GUARD + (size_t)BB * IMG + GUARD];

// ---------------- K1: NCHW -> NHWC transpose ----------------
__global__ __launch_bounds__(256) void transpose_kernel(const float* __restrict__ feat)
{
    __shared__ float tile[CC * 164];
    const int b = blockIdx.x / HH;
    const int y = blockIdx.x - b * HH;

    const float* src = feat + (size_t)b * IMG + (size_t)y * WW;
#pragma unroll
    for (int f = threadIdx.x; f < CC * (WW / 4); f += 256) {
        const int c  = f / (WW / 4);
        const int x4 = f - c * (WW / 4);
        const float4 v = __ldg(reinterpret_cast<const float4*>(src + (size_t)c * (HH * WW) + x4 * 4));
        *reinterpret_cast<float4*>(&tile[c * 164 + x4 * 4]) = v;
    }
    __syncthreads();

    float* dst = g_nhwc + GUARD + (size_t)b * IMG + (size_t)y * ROWF;
#pragma unroll
    for (int g = threadIdx.x; g < (WW * CC) / 4; g += 256) {
        const int x  = g >> 3;
        const int cg = g & 7;
        float4 v;
        v.x = tile[(4 * cg + 0) * 164 + x];
        v.y = tile[(4 * cg + 1) * 164 + x];
        v.z = tile[(4 * cg + 2) * 164 + x];
        v.w = tile[(4 * cg + 3) * 164 + x];
        *reinterpret_cast<float4*>(dst + (size_t)x * CC + 4 * cg) = v;
    }
}

// ---------------- K2: gather + blend, 2 rows per block ----------------
__global__ __launch_bounds__(512) void rroi_gather_kernel(
    const float* __restrict__ rois,
    float* __restrict__ out)
{
    __shared__ int    s_base[2 * PW];         // slot = row_local*64 + pw
    __shared__ float4 s_wv[2 * PW];
    __shared__ float  s_r[2][CC * 65];        // output tiles, odd stride (STS conflict-free)

    const int n   = blockIdx.x;
    const int tid = threadIdx.x;

    if (tid < 2 * PW) {
        const float2* rp = reinterpret_cast<const float2*>(rois + (size_t)n * 6);
        const float2 ra = __ldg(rp + 0);   // batch_idx, cx
        const float2 rb = __ldg(rp + 1);   // cy, h
        const float2 rc = __ldg(rp + 2);   // w, ang

        const int   bidx = (int)ra.x;
        const float cx = ra.y, cy = rb.x, hh = rb.y, ww = rc.x, ang = rc.y;

        const float theta = ang * 0.017453292519943295f;
        float sa, ca;
        sincosf(theta, &sa, &ca);

        const float Sx = ww * SCALE / (float)PW;
        const float Sy = hh * SCALE / (float)PH;
        const float dxc = -(float)PW * 0.5f;
        const float dyc = -(float)PH * 0.5f;
        const float Dx = cx * SCALE;
        const float Dy = cy * SCALE;

        const float M00 = ca * Sx;
        const float M01 = sa * Sy;
        const float M02 = M00 * dxc + M01 * dyc + Dx;
        const float M10 = -sa * Sx;
        const float M11 = ca * Sy;
        const float M12 = M10 * dxc + M11 * dyc + Dy;

        const float pw  = (float)(tid & (PW - 1));
        const float ph  = (float)(blockIdx.y * 2 + (tid >> 6));
        const float pw1 = pw + 1.0f;
        const float ph1 = ph + 1.0f;

        const float X0 = M00 * pw  + M01 * ph  + M02;
        const float X1 = M00 * pw  + M01 * ph1 + M02;
        const float X2 = M00 * pw1 + M01 * ph  + M02;
        const float X3 = M00 * pw1 + M01 * ph1 + M02;
        const float Y0 = M10 * pw  + M11 * ph  + M12;
        const float Y1 = M10 * pw  + M11 * ph1 + M12;
        const float Y2 = M10 * pw1 + M11 * ph  + M12;
        const float Y3 = M10 * pw1 + M11 * ph1 + M12;

        const float xmn = fminf(fminf(X0, X1), fminf(X2, X3));
        const float xmx = fmaxf(fmaxf(X0, X1), fmaxf(X2, X3));
        const float ymn = fminf(fminf(Y0, Y1), fminf(Y2, Y3));
        const float ymx = fmaxf(fmaxf(Y0, Y1), fmaxf(Y2, Y3));

        const float left   = fmaxf(floorf(xmn + 0.5f), 0.0f);
        const float right  = fminf(floorf(xmx + 0.5f), (float)(WW - 1));
        const float top    = fmaxf(floorf(ymn + 0.5f), 0.0f);
        const float bottom = fminf(floorf(ymx + 0.5f), (float)(HH - 1));

        const float bcx = (left + right) * 0.5f;
        const float bcy = (top + bottom) * 0.5f;

        const float bl = floorf(bcx);
        const float br = ceilf(bcx);
        const float bt = floorf(bcy);
        const float bb = ceilf(bcy);
        const float rx = bcx - bl;
        const float ry = bcy - bt;

        const bool vl = (bl > -1.0f) && (bl < (float)WW);
        const bool vr = (br > -1.0f) && (br < (float)WW);
        const bool vt = (bt > -1.0f) && (bt < (float)HH);
        const bool vb = (bb > -1.0f) && (bb < (float)HH);

        // nonzero weight implies ceil==floor+1 on that axis, so the fixed 2x2
        // patch at (yt..yt+1, xl..xl+1) is exact; zero-weight taps may touch
        // the zeroed guard band harmlessly.
        float wlt = (1.0f - rx) * (1.0f - ry);
        float wrt = rx * (1.0f - ry);
        float wlb = (1.0f - rx) * ry;
        float wrb = rx * ry;
        if (!(vt && vl)) wlt = 0.0f;
        if (!(vt && vr)) wrt = 0.0f;
        if (!(vb && vl)) wlb = 0.0f;
        if (!(vb && vr)) wrb = 0.0f;

        const int xl = (int)bl;
        const int yt = (int)bt;

        s_base[tid] = bidx * IMG + (yt * WW + xl) * CC;
        s_wv[tid]   = make_float4(wlt, wrt, wlb, wrb);
    }
    __syncthreads();

    const int bin = tid >> 3;            // 0..63
    const int cg  = tid & 7;             // 4-channel group
    const float* g = g_nhwc + GUARD;

#pragma unroll
    for (int rl = 0; rl < 2; rl++) {
        const int slot  = rl * PW + bin;
        const int base  = s_base[slot] + cg * 4;
        const float4 w  = s_wv[slot];

        const float4 t00 = *reinterpret_cast<const float4*>(g + base);
        const float4 t01 = *reinterpret_cast<const float4*>(g + base + CC);
        const float4 t10 = *reinterpret_cast<const float4*>(g + base + ROWF);
        const float4 t11 = *reinterpret_cast<const float4*>(g + base + ROWF + CC);

        float4 v;
        v.x = w.x * t00.x + w.y * t01.x + w.z * t10.x + w.w * t11.x;
        v.y = w.x * t00.y + w.y * t01.y + w.z * t10.y + w.w * t11.y;
        v.z = w.x * t00.z + w.y * t01.z + w.z * t10.z + w.w * t11.z;
        v.w = w.x * t00.w + w.y * t01.w + w.z * t10.w + w.w * t11.w;

        const int c0 = cg * 4;
        s_r[rl][(c0 + 0) * 65 + bin] = v.x;   // odd stride: conflict-free STS
        s_r[rl][(c0 + 1) * 65 + bin] = v.y;
        s_r[rl][(c0 + 2) * 65 + bin] = v.z;
        s_r[rl][(c0 + 3) * 65 + bin] = v.w;
    }
    __syncthreads();

    // epilogue: 4x LDS.32 (2-way conflicts max) + coalesced STG.128 per row
    const int c  = tid >> 4;             // 0..31
    const int x4 = tid & 15;             // 0..15
    const int r0 = blockIdx.y * 2;
    float* ob = out + (size_t)n * (CC * PH * PW) + (size_t)c * (PH * PW);

#pragma unroll
    for (int rl = 0; rl < 2; rl++) {
        const float* sr = &s_r[rl][c * 65 + x4 * 4];
        float4 v;
        v.x = sr[0];
        v.y = sr[1];
        v.z = sr[2];
        v.w = sr[3];
        *reinterpret_cast<float4*>(ob + (r0 + rl) * PW + x4 * 4) = v;
    }
}

}  // namespace

extern "C" void kernel_launch(void* const* d_in, const int* in_sizes, int n_in,
                              void* d_out, int out_size) {
    const float* features = (const float*)d_in[0];
    const float* rois     = (const float*)d_in[1];
    float* out            = (float*)d_out;

    const int N = in_sizes[1] / 6;  // 1024

    transpose_kernel<<<BB * HH, 256>>>(features);
    dim3 grid(N, PH / 2);
    rroi_gather_kernel<<<grid, 512>>>(rois, out);
}